// round 8
// baseline (speedup 1.0000x reference)
#include <cuda_runtime.h>
#include <cuda_bf16.h>
#include <cstdint>

#define BATCH 64
#define SEQT  80
#define EMBD  100
#define KX    128
#define UN    2048
#define NCTA  128
#define NTHR  256
#define STGB  24576   // Ahi 8K | Alo 8K | Bhi 4K | Blo 4K
#define NBUF  3
#define SM_RED (NBUF*STGB)
#define SM_TOTAL (SM_RED + 24576)

__device__ __nv_bfloat16 g_h0hi[2][BATCH*UN], g_h0lo[2][BATCH*UN];
__device__ __nv_bfloat16 g_h1hi[2][BATCH*UN], g_h1lo[2][BATCH*UN];
__device__ __nv_bfloat16 g_Xhi[SEQT*BATCH*KX], g_Xlo[SEQT*BATCH*KX];
__device__ __nv_bfloat16 g_Wh0hi[UN*UN], g_Wh0lo[UN*UN];   // [n][k]
__device__ __nv_bfloat16 g_Wx1hi[UN*UN], g_Wx1lo[UN*UN];
__device__ __nv_bfloat16 g_Wh1hi[UN*UN], g_Wh1lo[UN*UN];
__device__ __nv_bfloat16 g_Wx0hi[UN*KX], g_Wx0lo[UN*KX];
__device__ float    g_part[64*64*32];     // per-pair h1 partial [pair][row][col]
__device__ unsigned g_flag[64];
__device__ unsigned g_gbar;

extern __shared__ char smem[];

__device__ __forceinline__ uint32_t smem_u32(const void* p) {
    uint32_t a;
    asm("{ .reg .u64 t; cvta.to.shared.u64 t, %1; cvt.u32.u64 %0, t; }" : "=r"(a) : "l"(p));
    return a;
}
__device__ __forceinline__ void cpcg(uint32_t d, const void* s) {
    asm volatile("cp.async.cg.shared.global [%0], [%1], 16;" :: "r"(d), "l"(s));
}
#define CP_COMMIT() asm volatile("cp.async.commit_group;" ::: "memory")
#define CP_WAIT1()  asm volatile("cp.async.wait_group 1;" ::: "memory")
#define CP_WAIT0()  asm volatile("cp.async.wait_group 0;" ::: "memory")

__device__ __forceinline__ void mma16816(float c[4], const uint32_t a[4], const uint32_t b[2]) {
    asm volatile("mma.sync.aligned.m16n8k16.row.col.f32.bf16.bf16.f32 "
        "{%0,%1,%2,%3}, {%4,%5,%6,%7}, {%8,%9}, {%0,%1,%2,%3};"
        : "+f"(c[0]), "+f"(c[1]), "+f"(c[2]), "+f"(c[3])
        : "r"(a[0]), "r"(a[1]), "r"(a[2]), "r"(a[3]), "r"(b[0]), "r"(b[1]));
}
__device__ __forceinline__ void ldm4(uint32_t r[4], uint32_t addr) {
    asm volatile("ldmatrix.sync.aligned.m8n8.x4.shared.b16 {%0,%1,%2,%3}, [%4];"
        : "=r"(r[0]), "=r"(r[1]), "=r"(r[2]), "=r"(r[3]) : "r"(addr));
}

// ---- prep kernels ----
__global__ void wsplit(const float* __restrict__ src, __nv_bfloat16* __restrict__ hi,
                       __nv_bfloat16* __restrict__ lo, int K, int N, int Kpad) {
    __shared__ float tile[32][33];
    int kb = blockIdx.y * 32, nb = blockIdx.x * 32;
    int tx = threadIdx.x, ty = threadIdx.y;
    #pragma unroll
    for (int j = 0; j < 32; j += 8) {
        int k = kb + ty + j;
        tile[ty + j][tx] = (k < K) ? src[(size_t)k * N + nb + tx] : 0.0f;
    }
    __syncthreads();
    #pragma unroll
    for (int j = 0; j < 32; j += 8) {
        int n = nb + ty + j, k = kb + tx;
        if (k < Kpad) {
            float v = tile[tx][ty + j];
            __nv_bfloat16 h = __float2bfloat16(v);
            hi[(size_t)n * Kpad + k] = h;
            lo[(size_t)n * Kpad + k] = __float2bfloat16(v - __bfloat162float(h));
        }
    }
}
__global__ void xprep(const int* __restrict__ inputs, const float* __restrict__ emb) {
    int idx = blockIdx.x * blockDim.x + threadIdx.x;
    if (idx >= SEQT * BATCH * KX) return;
    int k = idx & 127, b = (idx >> 7) & 63, t = idx >> 13;
    float v = (k < EMBD) ? emb[(size_t)inputs[b * SEQT + t] * EMBD + k] : 0.0f;
    __nv_bfloat16 h = __float2bfloat16(v);
    g_Xhi[idx] = h;
    g_Xlo[idx] = __float2bfloat16(v - __bfloat162float(h));
}
__global__ void hzero() {
    int idx = blockIdx.x * blockDim.x + threadIdx.x;
    __nv_bfloat16 z = __float2bfloat16(0.0f);
    for (int i = idx; i < BATCH * UN; i += gridDim.x * blockDim.x) {
        g_h0hi[1][i] = z; g_h0lo[1][i] = z;
        g_h1hi[1][i] = z; g_h1lo[1][i] = z;
    }
    if (idx < 64) g_flag[idx] = 0u;
    if (idx == 0) g_gbar = 0u;
}

__device__ __forceinline__ void gbar(unsigned target) {
    __syncthreads();
    if (threadIdx.x == 0) {
        __threadfence();
        atomicAdd(&g_gbar, 1u);
        unsigned v;
        do {
            asm volatile("ld.acquire.gpu.u32 %0, [%1];" : "=r"(v) : "l"(&g_gbar) : "memory");
        } while (v < target);
    }
    __syncthreads();
}

struct Chunk {
    const __nv_bfloat16 *ah, *al, *bh, *bl;
    int astr, bstr;
};

// even CTA: [p>0: 15 Wh1-tail partial chunks] + 2 X + 32 Wh0  (h0 job)
// odd  CTA: 32 Wx1 + 17 Wh1  (h1 job, k-chunks 0..48)
__device__ __forceinline__ Chunk decode(bool even, int g, int p, int par0, int par1, int cb) {
    Chunk c; c.astr = UN; c.bstr = UN;
    if (even) {
        int gg = g;
        if (p > 0) {
            if (g < 15) {
                int kc = (17 + g) * 64;
                c.ah = g_h1hi[par1] + kc;  c.al = g_h1lo[par1] + kc;
                c.bh = g_Wh1hi + (size_t)cb * UN + kc;
                c.bl = g_Wh1lo + (size_t)cb * UN + kc;
                return c;
            }
            gg = g - 15;
        }
        if (gg < 2) {
            int kc = gg * 64;
            c.ah = g_Xhi + (size_t)p * BATCH * KX + kc;
            c.al = g_Xlo + (size_t)p * BATCH * KX + kc;  c.astr = KX;
            c.bh = g_Wx0hi + (size_t)cb * KX + kc;
            c.bl = g_Wx0lo + (size_t)cb * KX + kc;       c.bstr = KX;
        } else {
            int kc = (gg - 2) * 64;
            c.ah = g_h0hi[par0] + kc;  c.al = g_h0lo[par0] + kc;
            c.bh = g_Wh0hi + (size_t)cb * UN + kc;
            c.bl = g_Wh0lo + (size_t)cb * UN + kc;
        }
    } else {
        if (g < 32) {
            int kc = g * 64;
            c.ah = g_h0hi[par0] + kc;  c.al = g_h0lo[par0] + kc;
            c.bh = g_Wx1hi + (size_t)cb * UN + kc;
            c.bl = g_Wx1lo + (size_t)cb * UN + kc;
        } else {
            int kc = (g - 32) * 64;
            c.ah = g_h1hi[par1] + kc;  c.al = g_h1lo[par1] + kc;
            c.bh = g_Wh1hi + (size_t)cb * UN + kc;
            c.bl = g_Wh1lo + (size_t)cb * UN + kc;
        }
    }
    return c;
}

__device__ __forceinline__ void stage(const Chunk& c, uint32_t sb, int tid) {
    #pragma unroll
    for (int j = 0; j < 2; j++) {            // A hi/lo: 64 rows x 8 units
        int i = tid + NTHR * j;
        int r = i >> 3, q = i & 7;
        uint32_t off = (uint32_t)(r * 128 + ((q ^ (r & 7)) << 4));
        cpcg(sb + off,        c.ah + (size_t)r * c.astr + q * 8);
        cpcg(sb + 8192 + off, c.al + (size_t)r * c.astr + q * 8);
    }
    {                                        // B hi/lo: 32 rows x 8 units
        int r = tid >> 3, q = tid & 7;
        uint32_t off = (uint32_t)(r * 128 + ((q ^ (r & 7)) << 4));
        cpcg(sb + 16384 + off, c.bh + (size_t)r * c.bstr + q * 8);
        cpcg(sb + 20480 + off, c.bl + (size_t)r * c.bstr + q * 8);
    }
}

// Warp (wm, wk) computes M32 x N32 over its k16 quarter of the k64 chunk.
__device__ __forceinline__ void gemm_chunk(uint32_t sb, int wm, int wk, int lane,
                                           float acc[2][4][4]) {
    uint32_t ah[2][4], al[2][4];
    const int rA = lane & 15, uA = lane >> 4;
    #pragma unroll
    for (int mt = 0; mt < 2; mt++) {
        int row = wm * 32 + mt * 16 + rA;
        uint32_t ao = sb + (uint32_t)(row * 128 + ((((wk << 1) | uA) ^ (row & 7)) << 4));
        ldm4(ah[mt], ao);
        ldm4(al[mt], ao + 8192);
    }
    uint32_t b0h[4], b1h[4], b0l[4], b1l[4];
    uint32_t bbase = sb + 16384 + (uint32_t)(lane * 128);
    uint32_t o0 = (uint32_t)(((wk * 2)     ^ (lane & 7)) << 4);
    uint32_t o1 = (uint32_t)(((wk * 2 + 1) ^ (lane & 7)) << 4);
    ldm4(b0h, bbase + o0);        ldm4(b1h, bbase + o1);
    ldm4(b0l, bbase + 4096 + o0); ldm4(b1l, bbase + 4096 + o1);
    #pragma unroll
    for (int mt = 0; mt < 2; mt++)
        #pragma unroll
        for (int nt = 0; nt < 4; nt++) {
            uint32_t bh2[2] = {b0h[nt], b1h[nt]};
            uint32_t bl2[2] = {b0l[nt], b1l[nt]};
            mma16816(acc[mt][nt], ah[mt], bh2);
            mma16816(acc[mt][nt], ah[mt], bl2);
            mma16816(acc[mt][nt], al[mt], bh2);
        }
}

// 4-way k-quarter reduction; result lands in wk==0 warps.
__device__ __forceinline__ void reduce_acc(float* af, int wk, int tq, float* red) {
    __syncthreads();
    if (wk) {
        #pragma unroll
        for (int i = 0; i < 32; i++) red[i * 192 + (wk - 1) * 64 + tq] = af[i];
    }
    __syncthreads();
    if (!wk) {
        #pragma unroll
        for (int i = 0; i < 32; i++)
            af[i] += red[i * 192 + tq] + red[i * 192 + 64 + tq] + red[i * 192 + 128 + tq];
    }
}

__global__ void __launch_bounds__(NTHR, 1) rnn_mma(
    const float* __restrict__ b0, const float* __restrict__ b1,
    const float* __restrict__ Wo, const float* __restrict__ bo,
    float* __restrict__ out)
{
    const int tid = threadIdx.x;
    const int wid = tid >> 5, lane = tid & 31;
    const int wk = wid & 3, wm = wid >> 2;
    const int gr = lane >> 2, gc = lane & 3;
    const int pair = blockIdx.x >> 1;
    const bool even = !(blockIdx.x & 1);
    const int cb = pair * 32;
    const int tq = wm * 32 + lane;
    const float* bias = even ? b0 : b1;
    uint32_t su = smem_u32(smem);
    float* red = (float*)(smem + SM_RED);

    float bb[4][2];
    #pragma unroll
    for (int nt = 0; nt < 4; nt++) {
        int c = cb + nt * 8 + 2 * gc;
        bb[nt][0] = bias[c]; bb[nt][1] = bias[c + 1];
    }

    for (int p = 0; p <= SEQT; p++) {
        const int par0 = (p + 1) & 1, par1 = p & 1;
        const int nch = even ? (p == 0 ? 34 : (p == SEQT ? 15 : 49))
                             : (p == 0 ? 0 : 49);
        const bool hasMid = even && (p > 0);
        float acc[2][4][4] = {};
        float* af = &acc[0][0][0];

        if (nch > 0) {
            stage(decode(even, 0, p, par0, par1, cb), su, tid);
            CP_COMMIT();
            for (int g = 0; g < nch; g++) {
                if (g + 1 < nch) {
                    stage(decode(even, g + 1, p, par0, par1, cb),
                          su + (uint32_t)(((g + 1) % NBUF) * STGB), tid);
                    CP_COMMIT();
                    CP_WAIT1();
                } else {
                    CP_WAIT0();
                }
                __syncthreads();
                gemm_chunk(su + (uint32_t)((g % NBUF) * STGB), wm, wk, lane, acc);

                if (hasMid && g == 14) {
                    // ---- publish h1 partial for the paired odd CTA ----
                    reduce_acc(af, wk, tq, red);
                    if (wk == 0) {
                        float* dst = g_part + (size_t)pair * 64 * 32;
                        #pragma unroll
                        for (int mt = 0; mt < 2; mt++)
                            #pragma unroll
                            for (int nt = 0; nt < 4; nt++)
                                #pragma unroll
                                for (int e = 0; e < 4; e++) {
                                    int r = wm * 32 + mt * 16 + gr + 8 * (e >> 1);
                                    int cc = nt * 8 + 2 * gc + (e & 1);
                                    dst[r * 32 + cc] = acc[mt][nt][e];
                                }
                    }
                    __syncthreads();
                    if (tid == 0) {
                        __threadfence();
                        asm volatile("st.release.gpu.u32 [%0], %1;"
                                     :: "l"(&g_flag[pair]), "r"((unsigned)p) : "memory");
                    }
                    #pragma unroll
                    for (int i = 0; i < 32; i++) af[i] = 0.0f;
                }
            }

            // ---- final epilogue ----
            if (even) {
                if (p < SEQT) {
                    reduce_acc(af, wk, tq, red);
                    if (wk == 0) {
                        __nv_bfloat16* dhi = g_h0hi[p & 1];
                        __nv_bfloat16* dlo = g_h0lo[p & 1];
                        #pragma unroll
                        for (int mt = 0; mt < 2; mt++)
                            #pragma unroll
                            for (int nt = 0; nt < 4; nt++)
                                #pragma unroll
                                for (int hrow = 0; hrow < 2; hrow++) {
                                    int r = wm * 32 + mt * 16 + gr + 8 * hrow;
                                    int c0 = cb + nt * 8 + 2 * gc;
                                    float s0 = tanhf(acc[mt][nt][hrow * 2]     + bb[nt][0]);
                                    float s1 = tanhf(acc[mt][nt][hrow * 2 + 1] + bb[nt][1]);
                                    __nv_bfloat16 h0 = __float2bfloat16(s0), h1 = __float2bfloat16(s1);
                                    __nv_bfloat16 l0 = __float2bfloat16(s0 - __bfloat162float(h0));
                                    __nv_bfloat16 l1 = __float2bfloat16(s1 - __bfloat162float(h1));
                                    size_t off = (size_t)r * UN + c0;
                                    *(__nv_bfloat162*)(dhi + off) = __nv_bfloat162(h0, h1);
                                    *(__nv_bfloat162*)(dlo + off) = __nv_bfloat162(l0, l1);
                                }
                    }
                }
            } else {
                reduce_acc(af, wk, tq, red);
                if (wk == 0) {
                    // wait for even CTA's partial, then combine
                    unsigned v;
                    do {
                        asm volatile("ld.acquire.gpu.u32 %0, [%1];"
                                     : "=r"(v) : "l"(&g_flag[pair]) : "memory");
                    } while (v < (unsigned)p);
                    const float* src = g_part + (size_t)pair * 64 * 32;
                    __nv_bfloat16* dhi = g_h1hi[(p + 1) & 1];
                    __nv_bfloat16* dlo = g_h1lo[(p + 1) & 1];
                    #pragma unroll
                    for (int mt = 0; mt < 2; mt++)
                        #pragma unroll
                        for (int nt = 0; nt < 4; nt++)
                            #pragma unroll
                            for (int hrow = 0; hrow < 2; hrow++) {
                                int r = wm * 32 + mt * 16 + gr + 8 * hrow;
                                int cc = nt * 8 + 2 * gc;
                                float s0 = acc[mt][nt][hrow * 2]     + src[r * 32 + cc]     + bb[nt][0];
                                float s1 = acc[mt][nt][hrow * 2 + 1] + src[r * 32 + cc + 1] + bb[nt][1];
                                s0 = tanhf(s0); s1 = tanhf(s1);
                                __nv_bfloat16 h0 = __float2bfloat16(s0), h1 = __float2bfloat16(s1);
                                __nv_bfloat16 l0 = __float2bfloat16(s0 - __bfloat162float(h0));
                                __nv_bfloat16 l1 = __float2bfloat16(s1 - __bfloat162float(h1));
                                size_t off = (size_t)r * UN + cb + cc;
                                *(__nv_bfloat162*)(dhi + off) = __nv_bfloat162(h0, h1);
                                *(__nv_bfloat162*)(dlo + off) = __nv_bfloat162(l0, l1);
                            }
                }
            }
        }
        gbar((unsigned)(p + 1) * NCTA);
    }

    // ---- out[b] = sigmoid(h1_final . Wo + bo); h1_79 lives in parity 1 ----
    if (blockIdx.x == 0) {
        const __nv_bfloat16* hh = g_h1hi[1];
        const __nv_bfloat16* hl = g_h1lo[1];
        const float bof = bo[0];
        for (int r = wid; r < BATCH; r += 8) {
            float s = 0.0f;
            for (int k = lane; k < UN; k += 32)
                s += (__bfloat162float(hh[(size_t)r * UN + k]) +
                      __bfloat162float(hl[(size_t)r * UN + k])) * Wo[k];
            #pragma unroll
            for (int o = 16; o > 0; o >>= 1)
                s += __shfl_xor_sync(0xffffffffu, s, o);
            if (lane == 0) out[r] = 1.0f / (1.0f + expf(-(s + bof)));
        }
    }
}

extern "C" void kernel_launch(void* const* d_in, const int* in_sizes, int n_in,
                              void* d_out, int out_size)
{
    const int*   inputs = (const int*)  d_in[0];
    const float* emb    = (const float*)d_in[1];
    const float* Wx0    = (const float*)d_in[2];
    const float* Wh0    = (const float*)d_in[3];
    const float* b0     = (const float*)d_in[4];
    const float* Wx1    = (const float*)d_in[5];
    const float* Wh1    = (const float*)d_in[6];
    const float* b1     = (const float*)d_in[7];
    const float* Wo     = (const float*)d_in[8];
    const float* bo     = (const float*)d_in[9];
    float* out = (float*)d_out;

    __nv_bfloat16 *wh0h, *wh0l, *wx1h, *wx1l, *wh1h, *wh1l, *wx0h, *wx0l;
    cudaGetSymbolAddress((void**)&wh0h, g_Wh0hi); cudaGetSymbolAddress((void**)&wh0l, g_Wh0lo);
    cudaGetSymbolAddress((void**)&wx1h, g_Wx1hi); cudaGetSymbolAddress((void**)&wx1l, g_Wx1lo);
    cudaGetSymbolAddress((void**)&wh1h, g_Wh1hi); cudaGetSymbolAddress((void**)&wh1l, g_Wh1lo);
    cudaGetSymbolAddress((void**)&wx0h, g_Wx0hi); cudaGetSymbolAddress((void**)&wx0l, g_Wx0lo);

    dim3 tb(32, 8);
    wsplit<<<dim3(UN/32, UN/32), tb>>>(Wh0, wh0h, wh0l, UN, UN, UN);
    wsplit<<<dim3(UN/32, UN/32), tb>>>(Wx1, wx1h, wx1l, UN, UN, UN);
    wsplit<<<dim3(UN/32, UN/32), tb>>>(Wh1, wh1h, wh1l, UN, UN, UN);
    wsplit<<<dim3(UN/32, KX/32),  tb>>>(Wx0, wx0h, wx0l, EMBD, UN, KX);
    xprep<<<(SEQT*BATCH*KX + 255)/256, 256>>>(inputs, emb);
    hzero<<<256, 256>>>();

    cudaFuncSetAttribute(rnn_mma, cudaFuncAttributeMaxDynamicSharedMemorySize, SM_TOTAL);
    rnn_mma<<<NCTA, NTHR, SM_TOTAL>>>(b0, b1, Wo, bo, out);
}